// round 2
// baseline (speedup 1.0000x reference)
#include <cuda_runtime.h>
#include <cuda_fp16.h>
#include <cstdint>

// ---------------------------------------------------------------------------
// Problem constants
// ---------------------------------------------------------------------------
#define TOKENS  4096
#define IN_DIM  4096
#define OUT_DIM 4096
#define RANKL   16
#define LSCALE  2.0f   // lora_alpha / r = 32/16

// Converted activations + folded weight (static device scratch; allowed)
__device__ __half g_Xh[(size_t)TOKENS * IN_DIM];
__device__ __half g_Wh[(size_t)OUT_DIM * IN_DIM];

__constant__ float c_nf4[16] = {
    -1.0f, -0.6961928009986877f, -0.5250730514526367f, -0.39491748809814453f,
    -0.28444138169288635f, -0.18477343022823334f, -0.09105003625154495f, 0.0f,
    0.07958029955625534f, 0.16093020141124725f, 0.24611230194568634f, 0.33791524171829224f,
    0.44070982933044434f, 0.5626170039176941f, 0.7229568362236023f, 1.0f};

// ---------------------------------------------------------------------------
// Helpers (base-ISA only: cp.async, ldmatrix, mma.sync — NO tcgen05)
// ---------------------------------------------------------------------------
__device__ __forceinline__ uint32_t smem_u32(const void* p) {
    uint32_t a;
    asm("{ .reg .u64 t; cvta.to.shared.u64 t, %1; cvt.u32.u64 %0, t; }" : "=r"(a) : "l"(p));
    return a;
}

#define SWZ128(b) ((b) ^ (((b) >> 3) & 0x70))

__device__ __forceinline__ void cp16(uint32_t dst, const void* src) {
    asm volatile("cp.async.cg.shared.global [%0], [%1], 16;" :: "r"(dst), "l"(src));
}
#define CP_COMMIT() asm volatile("cp.async.commit_group;" ::: "memory")
#define CP_WAIT(n)  asm volatile("cp.async.wait_group %0;" :: "n"(n) : "memory")

__device__ __forceinline__ void ldm_x4(uint32_t& r0, uint32_t& r1, uint32_t& r2, uint32_t& r3,
                                       uint32_t addr) {
    asm volatile("ldmatrix.sync.aligned.m8n8.x4.shared.b16 {%0,%1,%2,%3}, [%4];"
                 : "=r"(r0), "=r"(r1), "=r"(r2), "=r"(r3) : "r"(addr));
}

__device__ __forceinline__ void mma16816(float& d0, float& d1, float& d2, float& d3,
                                         uint32_t a0, uint32_t a1, uint32_t a2, uint32_t a3,
                                         uint32_t b0, uint32_t b1) {
    asm volatile(
        "mma.sync.aligned.m16n8k16.row.col.f32.f16.f16.f32 "
        "{%0,%1,%2,%3}, {%4,%5,%6,%7}, {%8,%9}, {%0,%1,%2,%3};"
        : "+f"(d0), "+f"(d1), "+f"(d2), "+f"(d3)
        : "r"(a0), "r"(a1), "r"(a2), "r"(a3), "r"(b0), "r"(b1));
}

// ---------------------------------------------------------------------------
// Kernel 1: x fp32 -> fp16
// ---------------------------------------------------------------------------
__global__ void k_cvt_x(const float* __restrict__ x) {
    size_t i = (size_t)blockIdx.x * blockDim.x + threadIdx.x;
    float4 v = reinterpret_cast<const float4*>(x)[i];
    __half2 h01 = __floats2half2_rn(v.x, v.y);
    __half2 h23 = __floats2half2_rn(v.z, v.w);
    uint2 u;
    u.x = *reinterpret_cast<uint32_t*>(&h01);
    u.y = *reinterpret_cast<uint32_t*>(&h23);
    reinterpret_cast<uint2*>(g_Xh)[i] = u;
}

// ---------------------------------------------------------------------------
// Kernel 2: W' = NF4[codes]*scale + 2.0 * (B @ A)   -> fp16
// ---------------------------------------------------------------------------
__global__ void __launch_bounds__(256) k_build_w(
    const int* __restrict__ codes, const float* __restrict__ scales,
    const float* __restrict__ A, const float* __restrict__ Bm) {
    __shared__ float sB[64 * RANKL];
    __shared__ float snf4[16];
    int t = threadIdx.x;
    if (t < 16) snf4[t] = c_nf4[t];

    int k0 = blockIdx.x * 1024;
    int o0 = blockIdx.y * 64;

    for (int i = t; i < 64 * RANKL / 4; i += 256)
        reinterpret_cast<float4*>(sB)[i] =
            reinterpret_cast<const float4*>(Bm + (size_t)o0 * RANKL)[i];

    int kk = k0 + t * 4;
    float4 a[RANKL];
#pragma unroll
    for (int r = 0; r < RANKL; r++)
        a[r] = *reinterpret_cast<const float4*>(A + (size_t)r * IN_DIM + kk);
    __syncthreads();

    for (int rr = 0; rr < 64; rr++) {
        int o = o0 + rr;
        float4 acc = make_float4(0.f, 0.f, 0.f, 0.f);
#pragma unroll
        for (int r = 0; r < RANKL; r++) {
            float b = sB[rr * RANKL + r];
            acc.x = fmaf(b, a[r].x, acc.x);
            acc.y = fmaf(b, a[r].y, acc.y);
            acc.z = fmaf(b, a[r].z, acc.z);
            acc.w = fmaf(b, a[r].w, acc.w);
        }
        int4 cd = *reinterpret_cast<const int4*>(codes + (size_t)o * IN_DIM + kk);
        float sc = scales[(size_t)o * (IN_DIM / 64) + (kk >> 6)];
        float w0 = fmaf(snf4[cd.x], sc, LSCALE * acc.x);
        float w1 = fmaf(snf4[cd.y], sc, LSCALE * acc.y);
        float w2 = fmaf(snf4[cd.z], sc, LSCALE * acc.z);
        float w3 = fmaf(snf4[cd.w], sc, LSCALE * acc.w);
        __half2 h01 = __floats2half2_rn(w0, w1);
        __half2 h23 = __floats2half2_rn(w2, w3);
        uint2 u;
        u.x = *reinterpret_cast<uint32_t*>(&h01);
        u.y = *reinterpret_cast<uint32_t*>(&h23);
        *reinterpret_cast<uint2*>(g_Wh + (size_t)o * IN_DIM + kk) = u;
    }
}

// ---------------------------------------------------------------------------
// Kernel 3: GEMM  y[m,n] = sum_k Xh[m,k] * Wh[n,k]  (fp16 in, fp32 acc/out)
// HMMA mma.sync pipeline: 128x128x64 tile, 3-stage cp.async, SW128 smem.
// 8 warps = 2(M) x 4(N); warp tile 64x32; mma m16n8k16.
// ---------------------------------------------------------------------------
#define BM 128
#define BN 128
#define BK 64
#define NST 3
#define TILE_BYTES  (BM * BK * 2)            // 16384 per operand tile
#define STAGE_BYTES (2 * TILE_BYTES)         // 32768
#define GEMM_SMEM   (NST * STAGE_BYTES)      // 98304
#define KITERS      (IN_DIM / BK)            // 64

__device__ __forceinline__ void load_stage(uint32_t sA, uint32_t sB, int m0, int n0,
                                           int kq, int tid) {
    const __half* gx = g_Xh + (size_t)m0 * IN_DIM + (size_t)kq * BK;
#pragma unroll
    for (int i = 0; i < 4; i++) {            // A: 128 rows x 8 chunks(16B) = 1024
        int ch = tid + i * 256;
        int r = ch >> 3, c = ch & 7;
        cp16(sA + SWZ128(r * 128 + c * 16), gx + (size_t)r * IN_DIM + c * 8);
    }
    const __half* gw = g_Wh + (size_t)n0 * IN_DIM + (size_t)kq * BK;
#pragma unroll
    for (int i = 0; i < 4; i++) {            // B: 128 rows x 8 chunks = 1024
        int ch = tid + i * 256;
        int r = ch >> 3, c = ch & 7;
        cp16(sB + SWZ128(r * 128 + c * 16), gw + (size_t)r * IN_DIM + c * 8);
    }
}

__global__ void __launch_bounds__(256, 2) k_gemm(float* __restrict__ out) {
    extern __shared__ char dsm[];
    uint32_t sbase = smem_u32(dsm);

    int tid = threadIdx.x;
    int lane = tid & 31;
    int wid = tid >> 5;
    int wm = wid >> 2;    // 0..1  (M dimension)
    int wn = wid & 3;     // 0..3  (N dimension)
    int n0 = blockIdx.x * BN;
    int m0 = blockIdx.y * BM;

    float acc[4][4][4];
#pragma unroll
    for (int i = 0; i < 4; i++)
#pragma unroll
        for (int j = 0; j < 4; j++)
#pragma unroll
            for (int k = 0; k < 4; k++) acc[i][j][k] = 0.f;

    // prologue: fill stages 0,1
#pragma unroll
    for (int s = 0; s < NST - 1; s++) {
        load_stage(sbase + s * STAGE_BYTES, sbase + s * STAGE_BYTES + TILE_BYTES,
                   m0, n0, s, tid);
        CP_COMMIT();
    }

    int mi = lane >> 3;       // ldmatrix 8x8 sub-matrix index component
    int r8 = lane & 7;
    int rowhalf = (mi & 1) * 8 + r8;
    uint32_t khalf = (uint32_t)((mi >> 1) * 16);

    for (int it = 0; it < KITERS; it++) {
        CP_WAIT(1);           // stage `it` landed
        __syncthreads();      // all threads past compute(it-1); buffer (it-1)%3 free

        if (it + NST - 1 < KITERS) {
            int s = (it + NST - 1) % NST;
            load_stage(sbase + s * STAGE_BYTES, sbase + s * STAGE_BYTES + TILE_BYTES,
                       m0, n0, it + NST - 1, tid);
        }
        CP_COMMIT();          // unconditional: keeps group accounting uniform

        uint32_t sA = sbase + (it % NST) * STAGE_BYTES;
        uint32_t sB = sA + TILE_BYTES;

#pragma unroll
        for (int kk = 0; kk < 4; kk++) {     // four k16 steps within BK=64
            uint32_t a[4][4];
#pragma unroll
            for (int mt = 0; mt < 4; mt++) {
                int row = wm * 64 + mt * 16 + rowhalf;
                uint32_t col = ((uint32_t)(kk * 32) + khalf) ^ (uint32_t)((row & 7) << 4);
                ldm_x4(a[mt][0], a[mt][1], a[mt][2], a[mt][3],
                       sA + (uint32_t)row * 128 + col);
            }
            uint32_t b[2][4];
#pragma unroll
            for (int np = 0; np < 2; np++) {
                int row = wn * 32 + np * 16 + rowhalf;
                uint32_t col = ((uint32_t)(kk * 32) + khalf) ^ (uint32_t)((row & 7) << 4);
                ldm_x4(b[np][0], b[np][1], b[np][2], b[np][3],
                       sB + (uint32_t)row * 128 + col);
            }
#pragma unroll
            for (int mt = 0; mt < 4; mt++)
#pragma unroll
                for (int nt = 0; nt < 4; nt++) {
                    int np = nt >> 1, w = nt & 1;
                    mma16816(acc[mt][nt][0], acc[mt][nt][1], acc[mt][nt][2], acc[mt][nt][3],
                             a[mt][0], a[mt][1], a[mt][2], a[mt][3],
                             b[np][w], b[np][w + 2]);
                }
        }
    }

    // Epilogue: direct register -> gmem (float2 per tile-row, fully coalesced
    // 32B sectors across the 4 lanes sharing a row)
#pragma unroll
    for (int mt = 0; mt < 4; mt++) {
#pragma unroll
        for (int nt = 0; nt < 4; nt++) {
            int row0 = m0 + wm * 64 + mt * 16 + (lane >> 2);
            int col = n0 + wn * 32 + nt * 8 + (lane & 3) * 2;
            float2 v0 = make_float2(acc[mt][nt][0], acc[mt][nt][1]);
            float2 v1 = make_float2(acc[mt][nt][2], acc[mt][nt][3]);
            *reinterpret_cast<float2*>(out + (size_t)row0 * OUT_DIM + col) = v0;
            *reinterpret_cast<float2*>(out + (size_t)(row0 + 8) * OUT_DIM + col) = v1;
        }
    }
}

// ---------------------------------------------------------------------------
// Launch
// ---------------------------------------------------------------------------
extern "C" void kernel_launch(void* const* d_in, const int* in_sizes, int n_in,
                              void* d_out, int out_size) {
    const float* x      = (const float*)d_in[0];
    const int*   codes  = (const int*)d_in[1];
    const float* scales = (const float*)d_in[2];
    const float* lora_A = (const float*)d_in[3];
    const float* lora_B = (const float*)d_in[4];
    float* out = (float*)d_out;

    (void)in_sizes; (void)n_in; (void)out_size;

    // 1) x -> fp16
    k_cvt_x<<<(TOKENS * (size_t)IN_DIM / 4 + 255) / 256, 256>>>(x);

    // 2) folded weight (dequant + LoRA) -> fp16
    dim3 gdq(IN_DIM / 1024, OUT_DIM / 64);
    k_build_w<<<gdq, 256>>>(codes, scales, lora_A, lora_B);

    // 3) GEMM (HMMA mma.sync path — tcgen05 unavailable under this PTX target)
    cudaFuncSetAttribute(k_gemm, cudaFuncAttributeMaxDynamicSharedMemorySize, GEMM_SMEM);
    dim3 gg(OUT_DIM / BN, TOKENS / BM);
    k_gemm<<<gg, 256, GEMM_SMEM>>>(out);
}

// round 3
// speedup vs baseline: 1.3783x; 1.3783x over previous
#include <cuda_runtime.h>
#include <cuda_fp16.h>
#include <cstdint>

// ---------------------------------------------------------------------------
// Problem constants
// ---------------------------------------------------------------------------
#define TOKENS  4096
#define IN_DIM  4096
#define OUT_DIM 4096
#define RANKL   16
#define LSCALE  2.0f   // lora_alpha / r = 32/16
#define KPAD    64     // LoRA K-slab padded to one BK

// Static device scratch (allowed)
__device__ __half g_Xh[(size_t)TOKENS * IN_DIM];   // fp16 activations
__device__ __half g_Wh[(size_t)OUT_DIM * IN_DIM];  // fp16 dequantized weight
__device__ __half g_Xa[(size_t)TOKENS * KPAD];     // fp16 2*(x@A^T), padded to 64
__device__ __half g_Bh[(size_t)OUT_DIM * KPAD];    // fp16 B, padded to 64

__constant__ float c_nf4[16] = {
    -1.0f, -0.6961928009986877f, -0.5250730514526367f, -0.39491748809814453f,
    -0.28444138169288635f, -0.18477343022823334f, -0.09105003625154495f, 0.0f,
    0.07958029955625534f, 0.16093020141124725f, 0.24611230194568634f, 0.33791524171829224f,
    0.44070982933044434f, 0.5626170039176941f, 0.7229568362236023f, 1.0f};

// ---------------------------------------------------------------------------
// Helpers (base ISA only: cp.async / ldmatrix / mma.sync; tcgen05 unavailable
// under this toolchain's PTX target)
// ---------------------------------------------------------------------------
__device__ __forceinline__ uint32_t smem_u32(const void* p) {
    uint32_t a;
    asm("{ .reg .u64 t; cvta.to.shared.u64 t, %1; cvt.u32.u64 %0, t; }" : "=r"(a) : "l"(p));
    return a;
}

#define SWZ128(b) ((b) ^ (((b) >> 3) & 0x70))

__device__ __forceinline__ void cp16(uint32_t dst, const void* src) {
    asm volatile("cp.async.cg.shared.global [%0], [%1], 16;" :: "r"(dst), "l"(src));
}
#define CP_COMMIT() asm volatile("cp.async.commit_group;" ::: "memory")
#define CP_WAIT(n)  asm volatile("cp.async.wait_group %0;" :: "n"(n) : "memory")

__device__ __forceinline__ void ldm_x4(uint32_t& r0, uint32_t& r1, uint32_t& r2, uint32_t& r3,
                                       uint32_t addr) {
    asm volatile("ldmatrix.sync.aligned.m8n8.x4.shared.b16 {%0,%1,%2,%3}, [%4];"
                 : "=r"(r0), "=r"(r1), "=r"(r2), "=r"(r3) : "r"(addr));
}

__device__ __forceinline__ void mma16816(float& d0, float& d1, float& d2, float& d3,
                                         uint32_t a0, uint32_t a1, uint32_t a2, uint32_t a3,
                                         uint32_t b0, uint32_t b1) {
    asm volatile(
        "mma.sync.aligned.m16n8k16.row.col.f32.f16.f16.f32 "
        "{%0,%1,%2,%3}, {%4,%5,%6,%7}, {%8,%9}, {%0,%1,%2,%3};"
        : "+f"(d0), "+f"(d1), "+f"(d2), "+f"(d3)
        : "r"(a0), "r"(a1), "r"(a2), "r"(a3), "r"(b0), "r"(b1));
}

// ---------------------------------------------------------------------------
// Kernel 1: fused  (a) x fp32 -> fp16 into g_Xh   (b) g_Xa = fp16(2 * x @ A^T)
// Block: 256 threads handles 32 rows of x. A staged in smem per 1024-col chunk.
// Thread: rg = tid>>5 (4 rows), lane covers cols lane*4 + j*128.
// ---------------------------------------------------------------------------
#define XA_SMEM (16 * 1024 * 4)   // A chunk [16][1024] fp32 = 64KB

__global__ void __launch_bounds__(256) k_xa_cvt(const float* __restrict__ x,
                                                const float* __restrict__ A) {
    extern __shared__ float sA[];   // [16][1024]
    int tid = threadIdx.x;
    int rg = tid >> 5, lane = tid & 31;
    int r0 = blockIdx.x * 32 + rg * 4;

    float acc[4][RANKL];
#pragma unroll
    for (int rr = 0; rr < 4; rr++)
#pragma unroll
        for (int r = 0; r < RANKL; r++) acc[rr][r] = 0.f;

    for (int ch = 0; ch < 4; ch++) {
        // stage A[16][ch*1024 .. +1024) cooperatively (4096 float4 / 256 thr)
#pragma unroll
        for (int i = 0; i < 16; i++) {
            int idx = tid + i * 256;           // 0..4095 float4
            int arow = idx >> 8;               // 256 float4 per row
            int c4 = idx & 255;
            reinterpret_cast<float4*>(sA)[(size_t)arow * 256 + c4] =
                *reinterpret_cast<const float4*>(A + (size_t)arow * IN_DIM + ch * 1024 + c4 * 4);
        }
        __syncthreads();

#pragma unroll
        for (int j = 0; j < 8; j++) {
            int col = lane * 4 + j * 128;      // within chunk
            int gc = ch * 1024 + col;
            float4 a[RANKL];
#pragma unroll
            for (int r = 0; r < RANKL; r++)
                a[r] = *reinterpret_cast<const float4*>(sA + (size_t)r * 1024 + col);
#pragma unroll
            for (int rr = 0; rr < 4; rr++) {
                int row = r0 + rr;
                float4 xv = *reinterpret_cast<const float4*>(x + (size_t)row * IN_DIM + gc);
                // fp16 conversion store (coalesced: 32 lanes x 8B contiguous)
                __half2 h01 = __floats2half2_rn(xv.x, xv.y);
                __half2 h23 = __floats2half2_rn(xv.z, xv.w);
                uint2 u;
                u.x = *reinterpret_cast<uint32_t*>(&h01);
                u.y = *reinterpret_cast<uint32_t*>(&h23);
                *reinterpret_cast<uint2*>(g_Xh + (size_t)row * IN_DIM + gc) = u;
#pragma unroll
                for (int r = 0; r < RANKL; r++) {
                    acc[rr][r] = fmaf(xv.x, a[r].x, acc[rr][r]);
                    acc[rr][r] = fmaf(xv.y, a[r].y, acc[rr][r]);
                    acc[rr][r] = fmaf(xv.z, a[r].z, acc[rr][r]);
                    acc[rr][r] = fmaf(xv.w, a[r].w, acc[rr][r]);
                }
            }
        }
        __syncthreads();
    }

    // butterfly-reduce each acc over the 32 lanes
#pragma unroll
    for (int rr = 0; rr < 4; rr++)
#pragma unroll
        for (int r = 0; r < RANKL; r++)
#pragma unroll
            for (int s = 16; s > 0; s >>= 1)
                acc[rr][r] += __shfl_xor_sync(0xFFFFFFFFu, acc[rr][r], s);

    if (lane == 0) {
#pragma unroll
        for (int rr = 0; rr < 4; rr++) {
            int row = r0 + rr;
            __half* dst = g_Xa + (size_t)row * KPAD;
#pragma unroll
            for (int r = 0; r < RANKL; r++)
                dst[r] = __float2half(LSCALE * acc[rr][r]);
            // zero pad cols 16..63
            uint4 z = make_uint4(0, 0, 0, 0);
#pragma unroll
            for (int c = 16; c < KPAD; c += 8)
                *reinterpret_cast<uint4*>(dst + c) = z;
        }
    }
}

// ---------------------------------------------------------------------------
// Kernel 2: pure streaming dequant  W = NF4[code] * scale  -> fp16
// Thread handles 8 contiguous elements (within one 64-elem scale block).
// ---------------------------------------------------------------------------
__global__ void __launch_bounds__(256) k_dequant(const int* __restrict__ codes,
                                                 const float* __restrict__ scales) {
    __shared__ float lut[16];
    if (threadIdx.x < 16) lut[threadIdx.x] = c_nf4[threadIdx.x];
    __syncthreads();

    size_t i = (size_t)blockIdx.x * blockDim.x + threadIdx.x;   // 8 elems each
    size_t e = i * 8;
    int4 c0 = *reinterpret_cast<const int4*>(codes + e);
    int4 c1 = *reinterpret_cast<const int4*>(codes + e + 4);
    float sc = scales[e >> 6];
    __half2 h0 = __floats2half2_rn(lut[c0.x] * sc, lut[c0.y] * sc);
    __half2 h1 = __floats2half2_rn(lut[c0.z] * sc, lut[c0.w] * sc);
    __half2 h2 = __floats2half2_rn(lut[c1.x] * sc, lut[c1.y] * sc);
    __half2 h3 = __floats2half2_rn(lut[c1.z] * sc, lut[c1.w] * sc);
    uint4 u;
    u.x = *reinterpret_cast<uint32_t*>(&h0);
    u.y = *reinterpret_cast<uint32_t*>(&h1);
    u.z = *reinterpret_cast<uint32_t*>(&h2);
    u.w = *reinterpret_cast<uint32_t*>(&h3);
    *reinterpret_cast<uint4*>(g_Wh + e) = u;
}

// ---------------------------------------------------------------------------
// Kernel 3: B fp32 -> fp16, zero-padded to KPAD   (tiny: 4096 rows)
// ---------------------------------------------------------------------------
__global__ void k_prep_b(const float* __restrict__ Bm) {
    int n = blockIdx.x * blockDim.x + threadIdx.x;   // row
    const float4* src = reinterpret_cast<const float4*>(Bm + (size_t)n * RANKL);
    __half* dst = g_Bh + (size_t)n * KPAD;
    uint2 u[4];
#pragma unroll
    for (int q = 0; q < 4; q++) {
        float4 v = src[q];
        __half2 h01 = __floats2half2_rn(v.x, v.y);
        __half2 h23 = __floats2half2_rn(v.z, v.w);
        u[q].x = *reinterpret_cast<uint32_t*>(&h01);
        u[q].y = *reinterpret_cast<uint32_t*>(&h23);
    }
#pragma unroll
    for (int q = 0; q < 4; q++) *reinterpret_cast<uint2*>(dst + q * 4) = u[q];
    uint4 z = make_uint4(0, 0, 0, 0);
#pragma unroll
    for (int c = 16; c < KPAD; c += 8) *reinterpret_cast<uint4*>(dst + c) = z;
}

// ---------------------------------------------------------------------------
// Kernel 4: GEMM  y[m,n] = sum_k [Xh|Xa][m,k] * [Wh|Bh][n,k]
// 128x128 block, 4 warps (2x2), warp tile 64x64, 3-stage cp.async, SW128 smem.
// 65 K-iterations (64 main + 1 LoRA slab).
// ---------------------------------------------------------------------------
#define BM 128
#define BN 128
#define BK 64
#define NST 3
#define TILE_BYTES  (BM * BK * 2)            // 16384 per operand tile
#define STAGE_BYTES (2 * TILE_BYTES)         // 32768
#define GEMM_SMEM   (NST * STAGE_BYTES)      // 98304
#define KTOT        (IN_DIM / BK + 1)        // 65

__device__ __forceinline__ void load_stage(uint32_t sA, uint32_t sB,
                                           const __half* aptr, size_t astr,
                                           const __half* bptr, size_t bstr, int tid) {
#pragma unroll
    for (int i = 0; i < 8; i++) {            // A: 128 rows x 8 chunks(16B) = 1024
        int ch = tid + i * 128;
        int r = ch >> 3, c = ch & 7;
        cp16(sA + SWZ128(r * 128 + c * 16), aptr + (size_t)r * astr + c * 8);
    }
#pragma unroll
    for (int i = 0; i < 8; i++) {            // B: 128 rows x 8 chunks
        int ch = tid + i * 128;
        int r = ch >> 3, c = ch & 7;
        cp16(sB + SWZ128(r * 128 + c * 16), bptr + (size_t)r * bstr + c * 8);
    }
}

__device__ __forceinline__ void stage_src(int kq, int m0, int n0,
                                          const __half*& ap, size_t& as,
                                          const __half*& bp, size_t& bs) {
    if (kq < IN_DIM / BK) {
        ap = g_Xh + (size_t)m0 * IN_DIM + (size_t)kq * BK; as = IN_DIM;
        bp = g_Wh + (size_t)n0 * IN_DIM + (size_t)kq * BK; bs = IN_DIM;
    } else {
        ap = g_Xa + (size_t)m0 * KPAD; as = KPAD;
        bp = g_Bh + (size_t)n0 * KPAD; bs = KPAD;
    }
}

__global__ void __launch_bounds__(128, 2) k_gemm(float* __restrict__ out) {
    extern __shared__ char dsm[];
    uint32_t sbase = smem_u32(dsm);

    int tid = threadIdx.x;
    int lane = tid & 31;
    int wid = tid >> 5;
    int wm = wid >> 1;    // 0..1 (M)
    int wn = wid & 1;     // 0..1 (N)
    int n0 = blockIdx.x * BN;
    int m0 = blockIdx.y * BM;

    float acc[4][8][4];
#pragma unroll
    for (int i = 0; i < 4; i++)
#pragma unroll
        for (int j = 0; j < 8; j++)
#pragma unroll
            for (int k = 0; k < 4; k++) acc[i][j][k] = 0.f;

    // prologue: fill stages 0,1
#pragma unroll
    for (int s = 0; s < NST - 1; s++) {
        const __half *ap, *bp; size_t as, bs;
        stage_src(s, m0, n0, ap, as, bp, bs);
        load_stage(sbase + s * STAGE_BYTES, sbase + s * STAGE_BYTES + TILE_BYTES,
                   ap, as, bp, bs, tid);
        CP_COMMIT();
    }

    int mi = lane >> 3;
    int r8 = lane & 7;
    int rowhalf = (mi & 1) * 8 + r8;
    uint32_t khalf = (uint32_t)((mi >> 1) * 16);

    for (int it = 0; it < KTOT; it++) {
        CP_WAIT(1);
        __syncthreads();

        if (it + NST - 1 < KTOT) {
            int s = (it + NST - 1) % NST;
            const __half *ap, *bp; size_t as, bs;
            stage_src(it + NST - 1, m0, n0, ap, as, bp, bs);
            load_stage(sbase + s * STAGE_BYTES, sbase + s * STAGE_BYTES + TILE_BYTES,
                       ap, as, bp, bs, tid);
        }
        CP_COMMIT();

        uint32_t sA = sbase + (it % NST) * STAGE_BYTES;
        uint32_t sB = sA + TILE_BYTES;

#pragma unroll
        for (int kk = 0; kk < 4; kk++) {
            uint32_t a[4][4];
#pragma unroll
            for (int mt = 0; mt < 4; mt++) {
                int row = wm * 64 + mt * 16 + rowhalf;
                uint32_t col = ((uint32_t)(kk * 32) + khalf) ^ (uint32_t)((row & 7) << 4);
                ldm_x4(a[mt][0], a[mt][1], a[mt][2], a[mt][3],
                       sA + (uint32_t)row * 128 + col);
            }
            uint32_t b[4][4];
#pragma unroll
            for (int nb = 0; nb < 4; nb++) {
                int row = wn * 64 + nb * 16 + rowhalf;
                uint32_t col = ((uint32_t)(kk * 32) + khalf) ^ (uint32_t)((row & 7) << 4);
                ldm_x4(b[nb][0], b[nb][1], b[nb][2], b[nb][3],
                       sB + (uint32_t)row * 128 + col);
            }
#pragma unroll
            for (int mt = 0; mt < 4; mt++)
#pragma unroll
                for (int nb = 0; nb < 4; nb++)
#pragma unroll
                    for (int w = 0; w < 2; w++)
                        mma16816(acc[mt][nb * 2 + w][0], acc[mt][nb * 2 + w][1],
                                 acc[mt][nb * 2 + w][2], acc[mt][nb * 2 + w][3],
                                 a[mt][0], a[mt][1], a[mt][2], a[mt][3],
                                 b[nb][w], b[nb][w + 2]);
        }
    }

    // Epilogue: register -> gmem, float2 stores (coalesced 32B sectors)
#pragma unroll
    for (int mt = 0; mt < 4; mt++) {
#pragma unroll
        for (int nb = 0; nb < 4; nb++)
#pragma unroll
            for (int w = 0; w < 2; w++) {
                int nt = nb * 2 + w;
                int row0 = m0 + wm * 64 + mt * 16 + (lane >> 2);
                int col = n0 + wn * 64 + nb * 16 + w * 8 + (lane & 3) * 2;
                float2 v0 = make_float2(acc[mt][nt][0], acc[mt][nt][1]);
                float2 v1 = make_float2(acc[mt][nt][2], acc[mt][nt][3]);
                *reinterpret_cast<float2*>(out + (size_t)row0 * OUT_DIM + col) = v0;
                *reinterpret_cast<float2*>(out + (size_t)(row0 + 8) * OUT_DIM + col) = v1;
            }
    }
}

// ---------------------------------------------------------------------------
// Launch
// ---------------------------------------------------------------------------
extern "C" void kernel_launch(void* const* d_in, const int* in_sizes, int n_in,
                              void* d_out, int out_size) {
    const float* x      = (const float*)d_in[0];
    const int*   codes  = (const int*)d_in[1];
    const float* scales = (const float*)d_in[2];
    const float* lora_A = (const float*)d_in[3];
    const float* lora_B = (const float*)d_in[4];
    float* out = (float*)d_out;

    (void)in_sizes; (void)n_in; (void)out_size;

    // 1) streaming dequant (no LoRA math — folded into augmented K-slab)
    k_dequant<<<(OUT_DIM * (size_t)IN_DIM / 8 + 255) / 256, 256>>>(codes, scales);

    // 2) fused x->fp16 + Xa = fp16(2 * x @ A^T) (x read exactly once)
    cudaFuncSetAttribute(k_xa_cvt, cudaFuncAttributeMaxDynamicSharedMemorySize, XA_SMEM);
    k_xa_cvt<<<TOKENS / 32, 256, XA_SMEM>>>(x, lora_A);

    // 3) B -> fp16 padded
    k_prep_b<<<OUT_DIM / 256, 256>>>(lora_B);

    // 4) GEMM with augmented K (65 slabs)
    cudaFuncSetAttribute(k_gemm, cudaFuncAttributeMaxDynamicSharedMemorySize, GEMM_SMEM);
    dim3 gg(OUT_DIM / BN, TOKENS / BM);
    k_gemm<<<gg, 128, GEMM_SMEM>>>(out);
}

// round 4
// speedup vs baseline: 1.4718x; 1.0679x over previous
#include <cuda_runtime.h>
#include <cuda_fp16.h>
#include <cstdint>

// ---------------------------------------------------------------------------
// Problem constants
// ---------------------------------------------------------------------------
#define TOKENS  4096
#define IN_DIM  4096
#define OUT_DIM 4096
#define RANKL   16
#define LSCALE  2.0f   // lora_alpha / r = 32/16
#define KPAD    64     // LoRA K-slab padded to one BK

// Static device scratch (allowed)
__device__ __half g_Xh[(size_t)TOKENS * IN_DIM];   // fp16 activations
__device__ __half g_Wh[(size_t)OUT_DIM * IN_DIM];  // fp16 dequantized weight
__device__ __half g_Xa[(size_t)TOKENS * KPAD];     // fp16 2*(x@A^T), padded to 64
__device__ __half g_Bh[(size_t)OUT_DIM * KPAD];    // fp16 B, padded to 64

__constant__ float c_nf4[16] = {
    -1.0f, -0.6961928009986877f, -0.5250730514526367f, -0.39491748809814453f,
    -0.28444138169288635f, -0.18477343022823334f, -0.09105003625154495f, 0.0f,
    0.07958029955625534f, 0.16093020141124725f, 0.24611230194568634f, 0.33791524171829224f,
    0.44070982933044434f, 0.5626170039176941f, 0.7229568362236023f, 1.0f};

// ---------------------------------------------------------------------------
// Helpers (base ISA only: cp.async / ldmatrix / mma.sync)
// ---------------------------------------------------------------------------
__device__ __forceinline__ uint32_t smem_u32(const void* p) {
    uint32_t a;
    asm("{ .reg .u64 t; cvta.to.shared.u64 t, %1; cvt.u32.u64 %0, t; }" : "=r"(a) : "l"(p));
    return a;
}

#define SWZ128(b) ((b) ^ (((b) >> 3) & 0x70))

__device__ __forceinline__ void cp16(uint32_t dst, const void* src) {
    asm volatile("cp.async.cg.shared.global [%0], [%1], 16;" :: "r"(dst), "l"(src));
}
#define CP_COMMIT() asm volatile("cp.async.commit_group;" ::: "memory")
#define CP_WAIT(n)  asm volatile("cp.async.wait_group %0;" :: "n"(n) : "memory")

__device__ __forceinline__ void ldm_x4(uint32_t& r0, uint32_t& r1, uint32_t& r2, uint32_t& r3,
                                       uint32_t addr) {
    asm volatile("ldmatrix.sync.aligned.m8n8.x4.shared.b16 {%0,%1,%2,%3}, [%4];"
                 : "=r"(r0), "=r"(r1), "=r"(r2), "=r"(r3) : "r"(addr));
}

__device__ __forceinline__ void mma16816(float& d0, float& d1, float& d2, float& d3,
                                         uint32_t a0, uint32_t a1, uint32_t a2, uint32_t a3,
                                         uint32_t b0, uint32_t b1) {
    asm volatile(
        "mma.sync.aligned.m16n8k16.row.col.f32.f16.f16.f32 "
        "{%0,%1,%2,%3}, {%4,%5,%6,%7}, {%8,%9}, {%0,%1,%2,%3};"
        : "+f"(d0), "+f"(d1), "+f"(d2), "+f"(d3)
        : "r"(a0), "r"(a1), "r"(a2), "r"(a3), "r"(b0), "r"(b1));
}

// ---------------------------------------------------------------------------
// Kernel 1: fused  (a) x fp32 -> fp16 into g_Xh   (b) g_Xa = fp16(2 * x @ A^T)
// ---------------------------------------------------------------------------
#define XA_SMEM (16 * 1024 * 4)   // A chunk [16][1024] fp32 = 64KB

__global__ void __launch_bounds__(256) k_xa_cvt(const float* __restrict__ x,
                                                const float* __restrict__ A) {
    extern __shared__ float sA[];   // [16][1024]
    int tid = threadIdx.x;
    int rg = tid >> 5, lane = tid & 31;
    int r0 = blockIdx.x * 32 + rg * 4;

    float acc[4][RANKL];
#pragma unroll
    for (int rr = 0; rr < 4; rr++)
#pragma unroll
        for (int r = 0; r < RANKL; r++) acc[rr][r] = 0.f;

    for (int ch = 0; ch < 4; ch++) {
#pragma unroll
        for (int i = 0; i < 16; i++) {
            int idx = tid + i * 256;
            int arow = idx >> 8;
            int c4 = idx & 255;
            reinterpret_cast<float4*>(sA)[(size_t)arow * 256 + c4] =
                *reinterpret_cast<const float4*>(A + (size_t)arow * IN_DIM + ch * 1024 + c4 * 4);
        }
        __syncthreads();

#pragma unroll
        for (int j = 0; j < 8; j++) {
            int col = lane * 4 + j * 128;
            int gc = ch * 1024 + col;
            float4 a[RANKL];
#pragma unroll
            for (int r = 0; r < RANKL; r++)
                a[r] = *reinterpret_cast<const float4*>(sA + (size_t)r * 1024 + col);
#pragma unroll
            for (int rr = 0; rr < 4; rr++) {
                int row = r0 + rr;
                float4 xv = *reinterpret_cast<const float4*>(x + (size_t)row * IN_DIM + gc);
                __half2 h01 = __floats2half2_rn(xv.x, xv.y);
                __half2 h23 = __floats2half2_rn(xv.z, xv.w);
                uint2 u;
                u.x = *reinterpret_cast<uint32_t*>(&h01);
                u.y = *reinterpret_cast<uint32_t*>(&h23);
                *reinterpret_cast<uint2*>(g_Xh + (size_t)row * IN_DIM + gc) = u;
#pragma unroll
                for (int r = 0; r < RANKL; r++) {
                    acc[rr][r] = fmaf(xv.x, a[r].x, acc[rr][r]);
                    acc[rr][r] = fmaf(xv.y, a[r].y, acc[rr][r]);
                    acc[rr][r] = fmaf(xv.z, a[r].z, acc[rr][r]);
                    acc[rr][r] = fmaf(xv.w, a[r].w, acc[rr][r]);
                }
            }
        }
        __syncthreads();
    }

#pragma unroll
    for (int rr = 0; rr < 4; rr++)
#pragma unroll
        for (int r = 0; r < RANKL; r++)
#pragma unroll
            for (int s = 16; s > 0; s >>= 1)
                acc[rr][r] += __shfl_xor_sync(0xFFFFFFFFu, acc[rr][r], s);

    if (lane == 0) {
#pragma unroll
        for (int rr = 0; rr < 4; rr++) {
            int row = r0 + rr;
            __half* dst = g_Xa + (size_t)row * KPAD;
#pragma unroll
            for (int r = 0; r < RANKL; r++)
                dst[r] = __float2half(LSCALE * acc[rr][r]);
            uint4 z = make_uint4(0, 0, 0, 0);
#pragma unroll
            for (int c = 16; c < KPAD; c += 8)
                *reinterpret_cast<uint4*>(dst + c) = z;
        }
    }
}

// ---------------------------------------------------------------------------
// Kernel 2: pure streaming dequant  W = NF4[code] * scale  -> fp16
// ---------------------------------------------------------------------------
__global__ void __launch_bounds__(256) k_dequant(const int* __restrict__ codes,
                                                 const float* __restrict__ scales) {
    __shared__ float lut[16];
    if (threadIdx.x < 16) lut[threadIdx.x] = c_nf4[threadIdx.x];
    __syncthreads();

    size_t i = (size_t)blockIdx.x * blockDim.x + threadIdx.x;
    size_t e = i * 8;
    int4 c0 = *reinterpret_cast<const int4*>(codes + e);
    int4 c1 = *reinterpret_cast<const int4*>(codes + e + 4);
    float sc = scales[e >> 6];
    __half2 h0 = __floats2half2_rn(lut[c0.x] * sc, lut[c0.y] * sc);
    __half2 h1 = __floats2half2_rn(lut[c0.z] * sc, lut[c0.w] * sc);
    __half2 h2 = __floats2half2_rn(lut[c1.x] * sc, lut[c1.y] * sc);
    __half2 h3 = __floats2half2_rn(lut[c1.z] * sc, lut[c1.w] * sc);
    uint4 u;
    u.x = *reinterpret_cast<uint32_t*>(&h0);
    u.y = *reinterpret_cast<uint32_t*>(&h1);
    u.z = *reinterpret_cast<uint32_t*>(&h2);
    u.w = *reinterpret_cast<uint32_t*>(&h3);
    *reinterpret_cast<uint4*>(g_Wh + e) = u;
}

// ---------------------------------------------------------------------------
// Kernel 3: B fp32 -> fp16, zero-padded to KPAD
// ---------------------------------------------------------------------------
__global__ void k_prep_b(const float* __restrict__ Bm) {
    int n = blockIdx.x * blockDim.x + threadIdx.x;
    const float4* src = reinterpret_cast<const float4*>(Bm + (size_t)n * RANKL);
    __half* dst = g_Bh + (size_t)n * KPAD;
    uint2 u[4];
#pragma unroll
    for (int q = 0; q < 4; q++) {
        float4 v = src[q];
        __half2 h01 = __floats2half2_rn(v.x, v.y);
        __half2 h23 = __floats2half2_rn(v.z, v.w);
        u[q].x = *reinterpret_cast<uint32_t*>(&h01);
        u[q].y = *reinterpret_cast<uint32_t*>(&h23);
    }
#pragma unroll
    for (int q = 0; q < 4; q++) *reinterpret_cast<uint2*>(dst + q * 4) = u[q];
    uint4 z = make_uint4(0, 0, 0, 0);
#pragma unroll
    for (int c = 16; c < KPAD; c += 8) *reinterpret_cast<uint4*>(dst + c) = z;
}

// ---------------------------------------------------------------------------
// Kernel 4: GEMM  y[m,n] = sum_k [Xh|Xa][m,k] * [Wh|Bh][n,k]
// Block 64(M) x 128(N) x 64(K); 4 warps (2x2), warp tile 32x64; 3-stage
// cp.async; SW128 smem; 3 CTAs/SM (72KB smem) -> 3 warps/SMSP.
// ---------------------------------------------------------------------------
#define BM 64
#define BN 128
#define BK 64
#define NST 3
#define A_BYTES     (BM * BK * 2)            // 8192
#define B_BYTES     (BN * BK * 2)            // 16384
#define STAGE_BYTES (A_BYTES + B_BYTES)      // 24576
#define GEMM_SMEM   (NST * STAGE_BYTES)      // 73728
#define KMAIN       (IN_DIM / BK)            // 64
#define KTOT        (KMAIN + 1)              // 65

__global__ void __launch_bounds__(128, 3) k_gemm(float* __restrict__ out) {
    extern __shared__ char dsm[];
    uint32_t sbase = smem_u32(dsm);

    int tid = threadIdx.x;
    int lane = tid & 31;
    int wid = tid >> 5;
    int wm = wid >> 1;    // 0..1 (M)
    int wn = wid & 1;     // 0..1 (N)
    int n0 = blockIdx.x * BN;
    int m0 = blockIdx.y * BM;

    // --- precomputed per-thread load offsets (element units for gmem) ---
    uint32_t saoff[4]; int gaoff[4], gasoff[4];
#pragma unroll
    for (int i = 0; i < 4; i++) {            // A: 64 rows x 8 chunks = 512
        int ch = tid + i * 128;
        int r = ch >> 3, c = ch & 7;
        saoff[i] = SWZ128(r * 128 + c * 16);
        gaoff[i] = r * IN_DIM + c * 8;
        gasoff[i] = r * KPAD + c * 8;
    }
    uint32_t sboff[8]; int gboff[8], gbsoff[8];
#pragma unroll
    for (int i = 0; i < 8; i++) {            // B: 128 rows x 8 chunks = 1024
        int ch = tid + i * 128;
        int r = ch >> 3, c = ch & 7;
        sboff[i] = SWZ128(r * 128 + c * 16);
        gboff[i] = r * IN_DIM + c * 8;
        gbsoff[i] = r * KPAD + c * 8;
    }

    const __half* gXm = g_Xh + (size_t)m0 * IN_DIM;
    const __half* gWn = g_Wh + (size_t)n0 * IN_DIM;
    const __half* gXa = g_Xa + (size_t)m0 * KPAD;
    const __half* gBh = g_Bh + (size_t)n0 * KPAD;

    auto do_load = [&](int kq, int stage) {
        uint32_t sA = sbase + stage * STAGE_BYTES;
        uint32_t sB = sA + A_BYTES;
        if (kq < KMAIN) {
            const __half* ga = gXm + kq * BK;
            const __half* gb = gWn + kq * BK;
#pragma unroll
            for (int i = 0; i < 4; i++) cp16(sA + saoff[i], ga + gaoff[i]);
#pragma unroll
            for (int i = 0; i < 8; i++) cp16(sB + sboff[i], gb + gboff[i]);
        } else {
#pragma unroll
            for (int i = 0; i < 4; i++) cp16(sA + saoff[i], gXa + gasoff[i]);
#pragma unroll
            for (int i = 0; i < 8; i++) cp16(sB + sboff[i], gBh + gbsoff[i]);
        }
    };

    float acc[2][8][4];
#pragma unroll
    for (int i = 0; i < 2; i++)
#pragma unroll
        for (int j = 0; j < 8; j++)
#pragma unroll
            for (int k = 0; k < 4; k++) acc[i][j][k] = 0.f;

    // prologue: stages 0,1
    do_load(0, 0); CP_COMMIT();
    do_load(1, 1); CP_COMMIT();

    int mi = lane >> 3;
    int r8 = lane & 7;
    int rowhalf = (mi & 1) * 8 + r8;
    uint32_t khalf = (uint32_t)((mi >> 1) * 16);

    // precompute swizzled per-fragment base addresses (vary only by kk*32 XOR)
    uint32_t abase[2], bbase[4];
#pragma unroll
    for (int mt = 0; mt < 2; mt++) {
        int row = wm * 32 + mt * 16 + rowhalf;
        abase[mt] = (uint32_t)row * 128 + (khalf ^ (uint32_t)((row & 7) << 4));
    }
#pragma unroll
    for (int nb = 0; nb < 4; nb++) {
        int row = wn * 64 + nb * 16 + rowhalf;
        bbase[nb] = A_BYTES + (uint32_t)row * 128 + (khalf ^ (uint32_t)((row & 7) << 4));
    }

    for (int it = 0; it < KTOT; it++) {
        CP_WAIT(1);
        __syncthreads();

        if (it + NST - 1 < KTOT) do_load(it + NST - 1, (it + NST - 1) % NST);
        CP_COMMIT();

        uint32_t sS = sbase + (it % NST) * STAGE_BYTES;

#pragma unroll
        for (int kk = 0; kk < 4; kk++) {
            uint32_t kx = (uint32_t)(kk * 32);
            uint32_t a[2][4];
#pragma unroll
            for (int mt = 0; mt < 2; mt++)
                ldm_x4(a[mt][0], a[mt][1], a[mt][2], a[mt][3],
                       sS + (abase[mt] ^ kx));
            uint32_t b[4][4];
#pragma unroll
            for (int nb = 0; nb < 4; nb++)
                ldm_x4(b[nb][0], b[nb][1], b[nb][2], b[nb][3],
                       sS + (bbase[nb] ^ kx));
#pragma unroll
            for (int mt = 0; mt < 2; mt++)
#pragma unroll
                for (int nb = 0; nb < 4; nb++)
#pragma unroll
                    for (int w = 0; w < 2; w++)
                        mma16816(acc[mt][nb * 2 + w][0], acc[mt][nb * 2 + w][1],
                                 acc[mt][nb * 2 + w][2], acc[mt][nb * 2 + w][3],
                                 a[mt][0], a[mt][1], a[mt][2], a[mt][3],
                                 b[nb][w], b[nb][w + 2]);
        }
    }

    // Epilogue: register -> gmem, float2 stores
#pragma unroll
    for (int mt = 0; mt < 2; mt++) {
#pragma unroll
        for (int nb = 0; nb < 4; nb++)
#pragma unroll
            for (int w = 0; w < 2; w++) {
                int nt = nb * 2 + w;
                int row0 = m0 + wm * 32 + mt * 16 + (lane >> 2);
                int col = n0 + wn * 64 + nb * 16 + w * 8 + (lane & 3) * 2;
                float2 v0 = make_float2(acc[mt][nt][0], acc[mt][nt][1]);
                float2 v1 = make_float2(acc[mt][nt][2], acc[mt][nt][3]);
                *reinterpret_cast<float2*>(out + (size_t)row0 * OUT_DIM + col) = v0;
                *reinterpret_cast<float2*>(out + (size_t)(row0 + 8) * OUT_DIM + col) = v1;
            }
    }
}

// ---------------------------------------------------------------------------
// Launch
// ---------------------------------------------------------------------------
extern "C" void kernel_launch(void* const* d_in, const int* in_sizes, int n_in,
                              void* d_out, int out_size) {
    const float* x      = (const float*)d_in[0];
    const int*   codes  = (const int*)d_in[1];
    const float* scales = (const float*)d_in[2];
    const float* lora_A = (const float*)d_in[3];
    const float* lora_B = (const float*)d_in[4];
    float* out = (float*)d_out;

    (void)in_sizes; (void)n_in; (void)out_size;

    // 1) streaming dequant
    k_dequant<<<(OUT_DIM * (size_t)IN_DIM / 8 + 255) / 256, 256>>>(codes, scales);

    // 2) fused x->fp16 + Xa = fp16(2 * x @ A^T)
    cudaFuncSetAttribute(k_xa_cvt, cudaFuncAttributeMaxDynamicSharedMemorySize, XA_SMEM);
    k_xa_cvt<<<TOKENS / 32, 256, XA_SMEM>>>(x, lora_A);

    // 3) B -> fp16 padded
    k_prep_b<<<OUT_DIM / 256, 256>>>(lora_B);

    // 4) GEMM with augmented K (65 slabs)
    cudaFuncSetAttribute(k_gemm, cudaFuncAttributeMaxDynamicSharedMemorySize, GEMM_SMEM);
    dim3 gg(OUT_DIM / BN, TOKENS / BM);
    k_gemm<<<gg, 128, GEMM_SMEM>>>(out);
}

// round 5
// speedup vs baseline: 1.4925x; 1.0141x over previous
#include <cuda_runtime.h>
#include <cuda_fp16.h>
#include <cstdint>

// ---------------------------------------------------------------------------
// Problem constants
// ---------------------------------------------------------------------------
#define TOKENS  4096
#define IN_DIM  4096
#define OUT_DIM 4096
#define RANKL   16
#define LSCALE  2.0f   // lora_alpha / r = 32/16
#define KPAD    64     // LoRA K-slab padded to one BK

// Static device scratch (allowed)
__device__ __half g_Xh[(size_t)TOKENS * IN_DIM];   // fp16 activations
__device__ __half g_Wh[(size_t)OUT_DIM * IN_DIM];  // fp16 dequantized weight
__device__ __half g_Xa[(size_t)TOKENS * KPAD];     // fp16 2*(x@A^T), padded to 64
__device__ __half g_Bh[(size_t)OUT_DIM * KPAD];    // fp16 B, padded to 64

__constant__ float c_nf4[16] = {
    -1.0f, -0.6961928009986877f, -0.5250730514526367f, -0.39491748809814453f,
    -0.28444138169288635f, -0.18477343022823334f, -0.09105003625154495f, 0.0f,
    0.07958029955625534f, 0.16093020141124725f, 0.24611230194568634f, 0.33791524171829224f,
    0.44070982933044434f, 0.5626170039176941f, 0.7229568362236023f, 1.0f};

// ---------------------------------------------------------------------------
// Helpers (base ISA only: cp.async / ldmatrix / mma.sync)
// ---------------------------------------------------------------------------
__device__ __forceinline__ uint32_t smem_u32(const void* p) {
    uint32_t a;
    asm("{ .reg .u64 t; cvta.to.shared.u64 t, %1; cvt.u32.u64 %0, t; }" : "=r"(a) : "l"(p));
    return a;
}

#define SWZ128(b) ((b) ^ (((b) >> 3) & 0x70))

__device__ __forceinline__ void cp16(uint32_t dst, const void* src) {
    asm volatile("cp.async.cg.shared.global [%0], [%1], 16;" :: "r"(dst), "l"(src));
}
#define CP_COMMIT() asm volatile("cp.async.commit_group;" ::: "memory")
#define CP_WAIT(n)  asm volatile("cp.async.wait_group %0;" :: "n"(n) : "memory")

__device__ __forceinline__ void ldm_x4(uint32_t& r0, uint32_t& r1, uint32_t& r2, uint32_t& r3,
                                       uint32_t addr) {
    asm volatile("ldmatrix.sync.aligned.m8n8.x4.shared.b16 {%0,%1,%2,%3}, [%4];"
                 : "=r"(r0), "=r"(r1), "=r"(r2), "=r"(r3) : "r"(addr));
}

__device__ __forceinline__ void mma16816(float& d0, float& d1, float& d2, float& d3,
                                         uint32_t a0, uint32_t a1, uint32_t a2, uint32_t a3,
                                         uint32_t b0, uint32_t b1) {
    asm volatile(
        "mma.sync.aligned.m16n8k16.row.col.f32.f16.f16.f32 "
        "{%0,%1,%2,%3}, {%4,%5,%6,%7}, {%8,%9}, {%0,%1,%2,%3};"
        : "+f"(d0), "+f"(d1), "+f"(d2), "+f"(d3)
        : "r"(a0), "r"(a1), "r"(a2), "r"(a3), "r"(b0), "r"(b1));
}

// ---------------------------------------------------------------------------
// Kernel 1: fused  (a) x fp32 -> fp16 into g_Xh   (b) g_Xa = fp16(2 * x @ A^T)
// ---------------------------------------------------------------------------
#define XA_SMEM (16 * 1024 * 4)   // A chunk [16][1024] fp32 = 64KB

__global__ void __launch_bounds__(256) k_xa_cvt(const float* __restrict__ x,
                                                const float* __restrict__ A) {
    extern __shared__ float sA[];   // [16][1024]
    int tid = threadIdx.x;
    int rg = tid >> 5, lane = tid & 31;
    int r0 = blockIdx.x * 32 + rg * 4;

    float acc[4][RANKL];
#pragma unroll
    for (int rr = 0; rr < 4; rr++)
#pragma unroll
        for (int r = 0; r < RANKL; r++) acc[rr][r] = 0.f;

    for (int ch = 0; ch < 4; ch++) {
#pragma unroll
        for (int i = 0; i < 16; i++) {
            int idx = tid + i * 256;
            int arow = idx >> 8;
            int c4 = idx & 255;
            reinterpret_cast<float4*>(sA)[(size_t)arow * 256 + c4] =
                *reinterpret_cast<const float4*>(A + (size_t)arow * IN_DIM + ch * 1024 + c4 * 4);
        }
        __syncthreads();

#pragma unroll
        for (int j = 0; j < 8; j++) {
            int col = lane * 4 + j * 128;
            int gc = ch * 1024 + col;
            float4 a[RANKL];
#pragma unroll
            for (int r = 0; r < RANKL; r++)
                a[r] = *reinterpret_cast<const float4*>(sA + (size_t)r * 1024 + col);
#pragma unroll
            for (int rr = 0; rr < 4; rr++) {
                int row = r0 + rr;
                float4 xv = *reinterpret_cast<const float4*>(x + (size_t)row * IN_DIM + gc);
                __half2 h01 = __floats2half2_rn(xv.x, xv.y);
                __half2 h23 = __floats2half2_rn(xv.z, xv.w);
                uint2 u;
                u.x = *reinterpret_cast<uint32_t*>(&h01);
                u.y = *reinterpret_cast<uint32_t*>(&h23);
                *reinterpret_cast<uint2*>(g_Xh + (size_t)row * IN_DIM + gc) = u;
#pragma unroll
                for (int r = 0; r < RANKL; r++) {
                    acc[rr][r] = fmaf(xv.x, a[r].x, acc[rr][r]);
                    acc[rr][r] = fmaf(xv.y, a[r].y, acc[rr][r]);
                    acc[rr][r] = fmaf(xv.z, a[r].z, acc[rr][r]);
                    acc[rr][r] = fmaf(xv.w, a[r].w, acc[rr][r]);
                }
            }
        }
        __syncthreads();
    }

#pragma unroll
    for (int rr = 0; rr < 4; rr++)
#pragma unroll
        for (int r = 0; r < RANKL; r++)
#pragma unroll
            for (int s = 16; s > 0; s >>= 1)
                acc[rr][r] += __shfl_xor_sync(0xFFFFFFFFu, acc[rr][r], s);

    if (lane == 0) {
#pragma unroll
        for (int rr = 0; rr < 4; rr++) {
            int row = r0 + rr;
            __half* dst = g_Xa + (size_t)row * KPAD;
#pragma unroll
            for (int r = 0; r < RANKL; r++)
                dst[r] = __float2half(LSCALE * acc[rr][r]);
            uint4 z = make_uint4(0, 0, 0, 0);
#pragma unroll
            for (int c = 16; c < KPAD; c += 8)
                *reinterpret_cast<uint4*>(dst + c) = z;
        }
    }
}

// ---------------------------------------------------------------------------
// Kernel 2: pure streaming dequant  W = NF4[code] * scale  -> fp16
// ---------------------------------------------------------------------------
__global__ void __launch_bounds__(256) k_dequant(const int* __restrict__ codes,
                                                 const float* __restrict__ scales) {
    __shared__ float lut[16];
    if (threadIdx.x < 16) lut[threadIdx.x] = c_nf4[threadIdx.x];
    __syncthreads();

    size_t i = (size_t)blockIdx.x * blockDim.x + threadIdx.x;
    size_t e = i * 8;
    int4 c0 = *reinterpret_cast<const int4*>(codes + e);
    int4 c1 = *reinterpret_cast<const int4*>(codes + e + 4);
    float sc = scales[e >> 6];
    __half2 h0 = __floats2half2_rn(lut[c0.x] * sc, lut[c0.y] * sc);
    __half2 h1 = __floats2half2_rn(lut[c0.z] * sc, lut[c0.w] * sc);
    __half2 h2 = __floats2half2_rn(lut[c1.x] * sc, lut[c1.y] * sc);
    __half2 h3 = __floats2half2_rn(lut[c1.z] * sc, lut[c1.w] * sc);
    uint4 u;
    u.x = *reinterpret_cast<uint32_t*>(&h0);
    u.y = *reinterpret_cast<uint32_t*>(&h1);
    u.z = *reinterpret_cast<uint32_t*>(&h2);
    u.w = *reinterpret_cast<uint32_t*>(&h3);
    *reinterpret_cast<uint4*>(g_Wh + e) = u;
}

// ---------------------------------------------------------------------------
// Kernel 3: B fp32 -> fp16, zero-padded to KPAD
// ---------------------------------------------------------------------------
__global__ void k_prep_b(const float* __restrict__ Bm) {
    int n = blockIdx.x * blockDim.x + threadIdx.x;
    const float4* src = reinterpret_cast<const float4*>(Bm + (size_t)n * RANKL);
    __half* dst = g_Bh + (size_t)n * KPAD;
    uint2 u[4];
#pragma unroll
    for (int q = 0; q < 4; q++) {
        float4 v = src[q];
        __half2 h01 = __floats2half2_rn(v.x, v.y);
        __half2 h23 = __floats2half2_rn(v.z, v.w);
        u[q].x = *reinterpret_cast<uint32_t*>(&h01);
        u[q].y = *reinterpret_cast<uint32_t*>(&h23);
    }
#pragma unroll
    for (int q = 0; q < 4; q++) *reinterpret_cast<uint2*>(dst + q * 4) = u[q];
    uint4 z = make_uint4(0, 0, 0, 0);
#pragma unroll
    for (int c = 16; c < KPAD; c += 8) *reinterpret_cast<uint4*>(dst + c) = z;
}

// ---------------------------------------------------------------------------
// Kernel 4: GEMM  y[m,n] = sum_k [Xh|Xa][m,k] * [Wh|Bh][n,k]
// Block 128(M) x 128(N) x 64(K); 8 warps (4Mx2N), warp tile 32x64; 3-stage
// cp.async; SW128 smem; 2 CTAs/SM x 256thr -> 4 warps/SMSP (reg cap 128).
// Per-thread load offsets are a single base + linear deltas (32-row step
// preserves row&7, so SW128 swizzle is translation-invariant).
// ---------------------------------------------------------------------------
#define BM 128
#define BN 128
#define BK 64
#define NST 3
#define A_BYTES     (BM * BK * 2)            // 16384
#define B_BYTES     (BN * BK * 2)            // 16384
#define STAGE_BYTES (A_BYTES + B_BYTES)      // 32768
#define GEMM_SMEM   (NST * STAGE_BYTES)      // 98304
#define KMAIN       (IN_DIM / BK)            // 64
#define KTOT        (KMAIN + 1)              // 65

__global__ void __launch_bounds__(256, 2) k_gemm(float* __restrict__ out) {
    extern __shared__ char dsm[];
    uint32_t sbase = smem_u32(dsm);

    int tid = threadIdx.x;
    int lane = tid & 31;
    int wid = tid >> 5;
    int wm = wid >> 1;    // 0..3 (M)
    int wn = wid & 1;     // 0..1 (N)
    int n0 = blockIdx.x * BN;
    int m0 = blockIdx.y * BM;

    // --- single-base load offsets; i-th load = base + i*(32-row delta) ---
    int lr = tid >> 3, lc = tid & 7;                    // row 0..31, chunk col 0..7
    uint32_t s0 = SWZ128(lr * 128 + lc * 16);           // smem byte offset base
    int gmain = lr * IN_DIM + lc * 8;                   // gmem elem offset (stride 4096)
    int gside = lr * KPAD + lc * 8;                     // gmem elem offset (stride 64)

    const __half* gXm = g_Xh + (size_t)m0 * IN_DIM;
    const __half* gWn = g_Wh + (size_t)n0 * IN_DIM;
    const __half* gXa = g_Xa + (size_t)m0 * KPAD;
    const __half* gBh = g_Bh + (size_t)n0 * KPAD;

    auto do_load = [&](int kq, int stage) {
        uint32_t sA = sbase + stage * STAGE_BYTES;
        uint32_t sB = sA + A_BYTES;
        if (kq < KMAIN) {
            const __half* ga = gXm + kq * BK;
            const __half* gb = gWn + kq * BK;
#pragma unroll
            for (int i = 0; i < 4; i++)   // A: 128 rows, 32-row steps
                cp16(sA + s0 + i * (32 * 128), ga + gmain + i * (32 * IN_DIM));
#pragma unroll
            for (int i = 0; i < 4; i++)   // B: 128 rows
                cp16(sB + s0 + i * (32 * 128), gb + gmain + i * (32 * IN_DIM));
        } else {
#pragma unroll
            for (int i = 0; i < 4; i++)
                cp16(sA + s0 + i * (32 * 128), gXa + gside + i * (32 * KPAD));
#pragma unroll
            for (int i = 0; i < 4; i++)
                cp16(sB + s0 + i * (32 * 128), gBh + gside + i * (32 * KPAD));
        }
    };

    float acc[2][8][4];
#pragma unroll
    for (int i = 0; i < 2; i++)
#pragma unroll
        for (int j = 0; j < 8; j++)
#pragma unroll
            for (int k = 0; k < 4; k++) acc[i][j][k] = 0.f;

    // prologue: stages 0,1
    do_load(0, 0); CP_COMMIT();
    do_load(1, 1); CP_COMMIT();

    int mi = lane >> 3;
    int r8 = lane & 7;
    int rowhalf = (mi & 1) * 8 + r8;
    uint32_t khalf = (uint32_t)((mi >> 1) * 16);

    // swizzled fragment base addresses (vary per kk only by XOR of kk*32)
    uint32_t abase[2], bbase[4];
#pragma unroll
    for (int mt = 0; mt < 2; mt++) {
        int row = wm * 32 + mt * 16 + rowhalf;
        abase[mt] = (uint32_t)row * 128 + (khalf ^ (uint32_t)((row & 7) << 4));
    }
#pragma unroll
    for (int nb = 0; nb < 4; nb++) {
        int row = wn * 64 + nb * 16 + rowhalf;
        bbase[nb] = A_BYTES + (uint32_t)row * 128 + (khalf ^ (uint32_t)((row & 7) << 4));
    }

    for (int it = 0; it < KTOT; it++) {
        CP_WAIT(1);
        __syncthreads();

        if (it + NST - 1 < KTOT) do_load(it + NST - 1, (it + NST - 1) % NST);
        CP_COMMIT();

        uint32_t sS = sbase + (it % NST) * STAGE_BYTES;

#pragma unroll
        for (int kk = 0; kk < 4; kk++) {
            uint32_t kx = (uint32_t)(kk * 32);
            uint32_t a[2][4];
#pragma unroll
            for (int mt = 0; mt < 2; mt++)
                ldm_x4(a[mt][0], a[mt][1], a[mt][2], a[mt][3],
                       sS + (abase[mt] ^ kx));
            uint32_t b[4][4];
#pragma unroll
            for (int nb = 0; nb < 4; nb++)
                ldm_x4(b[nb][0], b[nb][1], b[nb][2], b[nb][3],
                       sS + (bbase[nb] ^ kx));
#pragma unroll
            for (int mt = 0; mt < 2; mt++)
#pragma unroll
                for (int nb = 0; nb < 4; nb++)
#pragma unroll
                    for (int w = 0; w < 2; w++)
                        mma16816(acc[mt][nb * 2 + w][0], acc[mt][nb * 2 + w][1],
                                 acc[mt][nb * 2 + w][2], acc[mt][nb * 2 + w][3],
                                 a[mt][0], a[mt][1], a[mt][2], a[mt][3],
                                 b[nb][w], b[nb][w + 2]);
        }
    }

    // Epilogue: register -> gmem, float2 stores
#pragma unroll
    for (int mt = 0; mt < 2; mt++) {
#pragma unroll
        for (int nb = 0; nb < 4; nb++)
#pragma unroll
            for (int w = 0; w < 2; w++) {
                int nt = nb * 2 + w;
                int row0 = m0 + wm * 32 + mt * 16 + (lane >> 2);
                int col = n0 + wn * 64 + nb * 16 + w * 8 + (lane & 3) * 2;
                float2 v0 = make_float2(acc[mt][nt][0], acc[mt][nt][1]);
                float2 v1 = make_float2(acc[mt][nt][2], acc[mt][nt][3]);
                *reinterpret_cast<float2*>(out + (size_t)row0 * OUT_DIM + col) = v0;
                *reinterpret_cast<float2*>(out + (size_t)(row0 + 8) * OUT_DIM + col) = v1;
            }
    }
}

// ---------------------------------------------------------------------------
// Launch
// ---------------------------------------------------------------------------
extern "C" void kernel_launch(void* const* d_in, const int* in_sizes, int n_in,
                              void* d_out, int out_size) {
    const float* x      = (const float*)d_in[0];
    const int*   codes  = (const int*)d_in[1];
    const float* scales = (const float*)d_in[2];
    const float* lora_A = (const float*)d_in[3];
    const float* lora_B = (const float*)d_in[4];
    float* out = (float*)d_out;

    (void)in_sizes; (void)n_in; (void)out_size;

    // 1) streaming dequant
    k_dequant<<<(OUT_DIM * (size_t)IN_DIM / 8 + 255) / 256, 256>>>(codes, scales);

    // 2) fused x->fp16 + Xa = fp16(2 * x @ A^T)
    cudaFuncSetAttribute(k_xa_cvt, cudaFuncAttributeMaxDynamicSharedMemorySize, XA_SMEM);
    k_xa_cvt<<<TOKENS / 32, 256, XA_SMEM>>>(x, lora_A);

    // 3) B -> fp16 padded
    k_prep_b<<<OUT_DIM / 256, 256>>>(lora_B);

    // 4) GEMM with augmented K (65 slabs)
    cudaFuncSetAttribute(k_gemm, cudaFuncAttributeMaxDynamicSharedMemorySize, GEMM_SMEM);
    dim3 gg(OUT_DIM / BN, TOKENS / BM);
    k_gemm<<<gg, 256, GEMM_SMEM>>>(out);
}